// round 16
// baseline (speedup 1.0000x reference)
#include <cuda_runtime.h>
#include <cuda_fp16.h>
#include <math.h>

#define NPIX 4140      // 46*90
#define CIN  256
#define HEADS 8
#define DHEAD 32
#define NTK  65        // key tiles of 64 (65*64 = 4160)
#define NSPLIT 2
#define TSPL 33        // tiles per split
#define LOG2E 1.4426950408889634f
#define NCP  (CIN / 2)              // 128 c-pairs

typedef unsigned int uint;

// ---------------- scratch (no allocations allowed) ----------------
__device__ float g_Q[CIN * NPIX];
__device__ float g_K[CIN * NPIX];
__device__ float g_V[CIN * NPIX];
__device__ float2 g_Po[NSPLIT][NCP * NPIX];   // unnormalized o partials [cp][n] (d-pairs)
__device__ float  g_Pl[NSPLIT][HEADS * NPIX]; // partial l
__device__ uint  g_Oh2[NCP * NPIX];     // attn out, fp16 hi pairs [cp][n]
__device__ uint  g_Ol2[NCP * NPIX];     // attn out, fp16 lo pairs
__device__ uint  g_Xh2[NCP * NPIX];     // query,  fp16 hi pairs [cp][n]
__device__ uint  g_Xl2[NCP * NPIX];     // query,  fp16 lo pairs
__device__ uint  g_Wh2[4 * CIN * NCP];  // q,k,v,p weights hi pairs [k][cp]
__device__ uint  g_Wl2[4 * CIN * NCP];  // weights lo pairs
__device__ float g_Lq[NTK * 64];        // log-quad bias * log2(e), padded

// ---------------- helpers ----------------
__device__ __forceinline__ float ex2(float x) {
    float y;
    asm("ex2.approx.f32 %0, %1;" : "=f"(y) : "f"(x));
    return y;
}

__device__ __forceinline__ uint packh2(float a, float b) {
    uint r;
    asm("cvt.rn.f16x2.f32 %0, %2, %1;" : "=r"(r) : "f"(a), "f"(b));
    return r;
}

__device__ __forceinline__ float2 unpackh2(uint u) {
    __half2 h = *reinterpret_cast<__half2*>(&u);
    return make_float2(__low2float(h), __high2float(h));
}

__device__ __forceinline__ void split_pair(float a, float b, uint& hi, uint& lo) {
    hi = packh2(a, b);
    float2 hv = unpackh2(hi);
    lo = packh2(a - hv.x, b - hv.y);
}

__device__ __forceinline__ void mma_f16(float c[4],
                                        uint a0, uint a1, uint a2, uint a3,
                                        uint b0, uint b1) {
    asm volatile(
        "mma.sync.aligned.m16n8k16.row.col.f32.f16.f16.f32 "
        "{%0,%1,%2,%3}, {%4,%5,%6,%7}, {%8,%9}, {%0,%1,%2,%3};"
        : "+f"(c[0]), "+f"(c[1]), "+f"(c[2]), "+f"(c[3])
        : "r"(a0), "r"(a1), "r"(a2), "r"(a3), "r"(b0), "r"(b1));
}

__device__ __forceinline__ void ldsm_x4(uint& r0, uint& r1, uint& r2, uint& r3,
                                        uint addr) {
    asm volatile("ldmatrix.sync.aligned.m8n8.x4.shared.b16 {%0,%1,%2,%3}, [%4];"
                 : "=r"(r0), "=r"(r1), "=r"(r2), "=r"(r3) : "r"(addr));
}
__device__ __forceinline__ void ldsm_x4_t(uint& r0, uint& r1, uint& r2, uint& r3,
                                          uint addr) {
    asm volatile("ldmatrix.sync.aligned.m8n8.x4.trans.shared.b16 {%0,%1,%2,%3}, [%4];"
                 : "=r"(r0), "=r"(r1), "=r"(r2), "=r"(r3) : "r"(addr));
}

__device__ __forceinline__ void cp_async16(void* dst, const void* src, int src_sz) {
    uint d = (uint)__cvta_generic_to_shared(dst);
    asm volatile("cp.async.cg.shared.global [%0], [%1], 16, %2;"
                 :: "r"(d), "l"(src), "r"(src_sz));
}
__device__ __forceinline__ void cp_commit() { asm volatile("cp.async.commit_group;"); }
__device__ __forceinline__ void cp_wait0()  { asm volatile("cp.async.wait_group 0;"); }

// ============================================================================
// Pre-split weights AND query -> fp16 (hi,lo) c-pairs (single launch)
// ============================================================================
#define NWP_TOT (4 * CIN * NCP)        // 131072 pair entries
#define NXP_TOT (NCP * NPIX)           // 529920 pair entries

__global__ __launch_bounds__(256)
void split_wx(const float* __restrict__ qw, const float* __restrict__ kw,
              const float* __restrict__ vw, const float* __restrict__ pw,
              const float* __restrict__ query)
{
    int i = blockIdx.x * 256 + threadIdx.x;
    if (i < NWP_TOT) {
        int m   = i >> 15;
        int rem = i & 32767;
        int k   = rem >> 7;
        int cp  = rem & 127;
        const float* W = (m == 0) ? qw : (m == 1) ? kw : (m == 2) ? vw : pw;
        uint hi, lo;
        split_pair(W[k * CIN + 2 * cp], W[k * CIN + 2 * cp + 1], hi, lo);
        g_Wh2[i] = hi;
        g_Wl2[i] = lo;
    } else {
        int j = i - NWP_TOT;
        if (j < NXP_TOT) {
            int cp = j / NPIX;
            int n  = j - cp * NPIX;
            uint hi, lo;
            split_pair(query[(2 * cp) * NPIX + n], query[(2 * cp + 1) * NPIX + n], hi, lo);
            g_Xh2[j] = hi;
            g_Xl2[j] = lo;
        }
    }
}

// ============================================================================
// 3-term fp16-split GEMM (hh + hl + lh), m16n8k16, pre-split operands.
// Tile 64k x 64n, 128 thr / 4 warps. k-step 32 (16 c-pairs), double-buffered.
// ============================================================================
#define WST 20
#define XST 72

__device__ __forceinline__
void gemm_core(const uint* __restrict__ Xh2, const uint* __restrict__ Xl2,
               const uint* __restrict__ Wh2, const uint* __restrict__ Wl2,
               const float* __restrict__ bias, float* __restrict__ Y)
{
    __shared__ uint sWh[2][64 * WST], sWl[2][64 * WST];
    __shared__ uint sXh[2][16 * XST], sXl[2][16 * XST];

    const int tid  = threadIdx.x;
    const int w    = tid >> 5;
    const int lane = tid & 31;
    const int g    = lane >> 2;
    const int tig  = lane & 3;
    const int k0   = blockIdx.y * 64;
    const int n0   = blockIdx.x * 64;

    {
        #pragma unroll
        for (int r = 0; r < 2; r++) {
            int idx = tid + 128 * r;
            int wk = idx >> 2, wcp = (idx & 3) * 4;
            cp_async16(&sWh[0][wk * WST + wcp], &Wh2[(k0 + wk) * NCP + wcp], 16);
            cp_async16(&sWl[0][wk * WST + wcp], &Wl2[(k0 + wk) * NCP + wcp], 16);
        }
        #pragma unroll
        for (int r = 0; r < 2; r++) {
            int idx = tid + 128 * r;
            int xcp = idx >> 4, xn = (idx & 15) * 4;
            int n = n0 + xn;
            int ok = (n < NPIX);
            cp_async16(&sXh[0][xcp * XST + xn], &Xh2[xcp * NPIX + (ok ? n : 0)], ok ? 16 : 0);
            cp_async16(&sXl[0][xcp * XST + xn], &Xl2[xcp * NPIX + (ok ? n : 0)], ok ? 16 : 0);
        }
        cp_commit();
    }

    float acc[8][4];
    #pragma unroll
    for (int nb = 0; nb < 8; nb++)
        #pragma unroll
        for (int i = 0; i < 4; i++) acc[nb][i] = 0.f;

    cp_wait0();
    __syncthreads();

    #pragma unroll
    for (int it = 0; it < 8; it++) {
        const int cur = it & 1;
        const int nxt = cur ^ 1;
        const bool more = (it + 1 < 8);

        if (more) {
            const int cc2 = (it + 1) * 16;
            #pragma unroll
            for (int r = 0; r < 2; r++) {
                int idx = tid + 128 * r;
                int wk = idx >> 2, wcp = (idx & 3) * 4;
                cp_async16(&sWh[nxt][wk * WST + wcp],
                           &Wh2[(k0 + wk) * NCP + cc2 + wcp], 16);
                cp_async16(&sWl[nxt][wk * WST + wcp],
                           &Wl2[(k0 + wk) * NCP + cc2 + wcp], 16);
            }
            #pragma unroll
            for (int r = 0; r < 2; r++) {
                int idx = tid + 128 * r;
                int xcp = idx >> 4, xn = (idx & 15) * 4;
                int n = n0 + xn;
                int ok = (n < NPIX);
                cp_async16(&sXh[nxt][xcp * XST + xn],
                           &Xh2[(cc2 + xcp) * NPIX + (ok ? n : 0)], ok ? 16 : 0);
                cp_async16(&sXl[nxt][xcp * XST + xn],
                           &Xl2[(cc2 + xcp) * NPIX + (ok ? n : 0)], ok ? 16 : 0);
            }
            cp_commit();
        }

        #pragma unroll
        for (int kb = 0; kb < 2; kb++) {
            const int ar = (w * 16 + g) * WST + kb * 8 + tig;
            uint ah0 = sWh[cur][ar];
            uint ah1 = sWh[cur][ar + 8 * WST];
            uint ah2 = sWh[cur][ar + 4];
            uint ah3 = sWh[cur][ar + 8 * WST + 4];
            uint al0 = sWl[cur][ar];
            uint al1 = sWl[cur][ar + 8 * WST];
            uint al2 = sWl[cur][ar + 4];
            uint al3 = sWl[cur][ar + 8 * WST + 4];
            const int br0 = (kb * 8 + tig) * XST + g;
            const int br1 = br0 + 4 * XST;
            #pragma unroll
            for (int nb = 0; nb < 8; nb++) {
                uint bh0 = sXh[cur][br0 + nb * 8];
                uint bh1 = sXh[cur][br1 + nb * 8];
                uint bl0 = sXl[cur][br0 + nb * 8];
                uint bl1 = sXl[cur][br1 + nb * 8];
                mma_f16(acc[nb], ah0, ah1, ah2, ah3, bh0, bh1);
                mma_f16(acc[nb], ah0, ah1, ah2, ah3, bl0, bl1);
                mma_f16(acc[nb], al0, al1, al2, al3, bh0, bh1);
            }
        }

        if (more) cp_wait0();
        __syncthreads();
    }

    const int r0 = k0 + w * 16 + g;
    const int r1 = r0 + 8;
    const float bv0 = __ldg(&bias[r0]);
    const float bv1 = __ldg(&bias[r1]);
    #pragma unroll
    for (int nb = 0; nb < 8; nb++) {
        int n = n0 + nb * 8 + 2 * tig;
        if (n < NPIX) {
            float2 y0 = make_float2(acc[nb][0] + bv0, acc[nb][1] + bv0);
            float2 y1 = make_float2(acc[nb][2] + bv1, acc[nb][3] + bv1);
            *(float2*)&Y[r0 * NPIX + n] = y0;
            *(float2*)&Y[r1 * NPIX + n] = y1;
        }
    }
}

__global__ __launch_bounds__(128)
void gemm_qkv(const float* __restrict__ qb, const float* __restrict__ kb,
              const float* __restrict__ vb, const float* __restrict__ lq)
{
    int z = blockIdx.z;
    if (z == 0 && blockIdx.x == 0 && blockIdx.y == 0) {
        for (int i = threadIdx.x; i < NTK * 64; i += 128)
            g_Lq[i] = (i < NPIX) ? lq[i] * LOG2E : -1e30f;
    }
    const float* B = (z == 0) ? qb : (z == 1) ? kb : vb;
    float* Y       = (z == 0) ? g_Q : (z == 1) ? g_K : g_V;
    gemm_core(g_Xh2, g_Xl2, g_Wh2 + z * CIN * NCP, g_Wl2 + z * CIN * NCP, B, Y);
}

__global__ __launch_bounds__(128)
void gemm_proj(const float* __restrict__ B, float* __restrict__ Y)
{
    gemm_core(g_Oh2, g_Ol2, g_Wh2 + 3 * CIN * NCP, g_Wl2 + 3 * CIN * NCP, B, Y);
}

// ============================================================================
// Flash attention, fp16 m16n8k16, fixed-shift base-2 softmax, split-K (z=0,1),
// K/V fragments via ldmatrix. Partials written [cp][n] float2 (coalesced for
// the reduce).
//   Grid 17 x 8 x 2 = 272 blocks of 512 thr -> 2 CTAs/SM (32 warps/SM).
// ============================================================================
#define KSW 36     // words per K d-row (64 keys f16 = 32 words + 4 pad)
#define VSW 36     // words per V d-row (32 key-pair words + 4 pad)

__global__ __launch_bounds__(512, 2)
void attn_kernel()
{
    __shared__ uint sK[2][32 * KSW];
    __shared__ uint sV[2][32 * VSW];

    const int tid  = threadIdx.x;
    const int lane = tid & 31;
    const int w    = tid >> 5;
    const int g    = lane >> 2;
    const int tig  = lane & 3;
    const int h    = blockIdx.y;
    const int qb   = blockIdx.x;
    const int z    = blockIdx.z;

    const int t0    = z * TSPL;
    const int t_end = (t0 + TSPL < NTK) ? (t0 + TSPL) : NTK;

    const int q_row0 = qb * 256 + w * 16 + g;
    const int q_row1 = q_row0 + 8;

    const int fd  = tid >> 4;
    const int fkc = tid & 15;

    const uint skb0 = (uint)__cvta_generic_to_shared(&sK[0][0]);
    const uint skb1 = (uint)__cvta_generic_to_shared(&sK[1][0]);
    const uint svb0 = (uint)__cvta_generic_to_shared(&sV[0][0]);
    const uint svb1 = (uint)__cvta_generic_to_shared(&sV[1][0]);

    const uint koff = (uint)lane * KSW;
    const uint vrow = ((lane >> 4) * 8 + (lane & 7)) * VSW + ((lane >> 3) & 1) * 4;

    // ---- Q fragments, fp16 (scale includes log2 e) ----
    const float scale = 0.17677669529663687f * LOG2E;
    const int r0 = (q_row0 < NPIX) ? q_row0 : (NPIX - 1);
    const int r1 = (q_row1 < NPIX) ? q_row1 : (NPIX - 1);
    uint qa[2][4];
    #pragma unroll
    for (int kc = 0; kc < 2; kc++) {
        int d0 = kc * 16 + 2 * tig;
        const float* Qh = g_Q + (size_t)h * DHEAD * NPIX;
        qa[kc][0] = packh2(Qh[(d0)     * NPIX + r0] * scale, Qh[(d0 + 1) * NPIX + r0] * scale);
        qa[kc][1] = packh2(Qh[(d0)     * NPIX + r1] * scale, Qh[(d0 + 1) * NPIX + r1] * scale);
        qa[kc][2] = packh2(Qh[(d0 + 8) * NPIX + r0] * scale, Qh[(d0 + 9) * NPIX + r0] * scale);
        qa[kc][3] = packh2(Qh[(d0 + 8) * NPIX + r1] * scale, Qh[(d0 + 9) * NPIX + r1] * scale);
    }

    float o[4][4];
    #pragma unroll
    for (int db = 0; db < 4; db++)
        #pragma unroll
        for (int j = 0; j < 4; j++) o[db][j] = 0.f;

    float l0 = 0.f, l1 = 0.f;
    float4 rk, rv;

    const float* Kbase = g_K + (size_t)h * DHEAD * NPIX;
    const float* Vbase = g_V + (size_t)h * DHEAD * NPIX;

    // ---------- prologue ----------
    {
        int key0 = t0 * 64 + fkc * 4;
        rk = *(const float4*)&Kbase[fd * NPIX + key0];
        rv = *(const float4*)&Vbase[fd * NPIX + key0];
        uint2 kk = make_uint2(packh2(rk.x, rk.y), packh2(rk.z, rk.w));
        uint2 vv = make_uint2(packh2(rv.x, rv.y), packh2(rv.z, rv.w));
        *(uint2*)&sK[0][fd * KSW + fkc * 2] = kk;
        *(uint2*)&sV[0][fd * VSW + fkc * 2] = vv;
    }
    __syncthreads();

    for (int t = t0; t < t_end; t++) {
        const int cur = (t - t0) & 1;
        const bool more = (t + 1 < t_end);
        const uint skc = cur ? skb1 : skb0;
        const uint svc = cur ? svb1 : svb0;

        if (more) {
            int key0 = (t + 1) * 64 + fkc * 4;
            bool ok = (key0 < NPIX);
            int keyc = ok ? key0 : 0;
            float4 ka = *(const float4*)&Kbase[fd * NPIX + keyc];
            float4 va = *(const float4*)&Vbase[fd * NPIX + keyc];
            rk = ok ? ka : make_float4(0.f, 0.f, 0.f, 0.f);
            rv = ok ? va : make_float4(0.f, 0.f, 0.f, 0.f);
        }

        // ---- S = Q K^T ----
        float c[8][4];
        #pragma unroll
        for (int nb = 0; nb < 8; nb++) {
            c[nb][0] = c[nb][1] = c[nb][2] = c[nb][3] = 0.f;
            uint b00, b01, b10, b11;
            ldsm_x4_t(b00, b01, b10, b11, skc + (koff + nb * 4) * 4);
            mma_f16(c[nb], qa[0][0], qa[0][1], qa[0][2], qa[0][3], b00, b01);
            mma_f16(c[nb], qa[1][0], qa[1][1], qa[1][2], qa[1][3], b10, b11);
        }

        // ---- fused bias + exp2 + pack + PV ----
        #pragma unroll
        for (int kc = 0; kc < 4; kc++) {
            const int nb0 = 2 * kc, nb1 = 2 * kc + 1;
            float2 lb0 = *(const float2*)&g_Lq[t * 64 + nb0 * 8 + 2 * tig];
            float2 lb1 = *(const float2*)&g_Lq[t * 64 + nb1 * 8 + 2 * tig];
            float p00 = ex2(c[nb0][0] + lb0.x);
            float p01 = ex2(c[nb0][1] + lb0.y);
            float p02 = ex2(c[nb0][2] + lb0.x);
            float p03 = ex2(c[nb0][3] + lb0.y);
            float p10 = ex2(c[nb1][0] + lb1.x);
            float p11 = ex2(c[nb1][1] + lb1.y);
            float p12 = ex2(c[nb1][2] + lb1.x);
            float p13 = ex2(c[nb1][3] + lb1.y);
            l0 += (p00 + p01) + (p10 + p11);
            l1 += (p02 + p03) + (p12 + p13);
            uint pa0 = packh2(p00, p01);
            uint pa1 = packh2(p02, p03);
            uint pa2 = packh2(p10, p11);
            uint pa3 = packh2(p12, p13);
            #pragma unroll
            for (int dbp = 0; dbp < 2; dbp++) {
                uint v00, v01, v10, v11;
                uint addr = svc + (vrow + dbp * 16 * VSW + kc * 8) * 4;
                ldsm_x4(v00, v01, v10, v11, addr);
                mma_f16(o[2 * dbp],     pa0, pa1, pa2, pa3, v00, v01);
                mma_f16(o[2 * dbp + 1], pa0, pa1, pa2, pa3, v10, v11);
            }
        }

        if (more) {
            const int nxt = cur ^ 1;
            uint2 kk = make_uint2(packh2(rk.x, rk.y), packh2(rk.z, rk.w));
            uint2 vv = make_uint2(packh2(rv.x, rv.y), packh2(rv.z, rv.w));
            *(uint2*)&sK[nxt][fd * KSW + fkc * 2] = kk;
            *(uint2*)&sV[nxt][fd * VSW + fkc * 2] = vv;
        }
        __syncthreads();
    }

    // ---- partial epilogue: quad-reduce l, write [cp][n] float2 partials ----
    l0 += __shfl_xor_sync(0xffffffffu, l0, 1);
    l0 += __shfl_xor_sync(0xffffffffu, l0, 2);
    l1 += __shfl_xor_sync(0xffffffffu, l1, 1);
    l1 += __shfl_xor_sync(0xffffffffu, l1, 2);
    if (tig == 0) {
        if (q_row0 < NPIX) g_Pl[z][h * NPIX + q_row0] = l0;
        if (q_row1 < NPIX) g_Pl[z][h * NPIX + q_row1] = l1;
    }
    #pragma unroll
    for (int db = 0; db < 4; db++) {
        int cpg = h * 16 + db * 4 + tig;     // global c-pair index
        if (q_row0 < NPIX)
            g_Po[z][cpg * NPIX + q_row0] = make_float2(o[db][0], o[db][1]);
        if (q_row1 < NPIX)
            g_Po[z][cpg * NPIX + q_row1] = make_float2(o[db][2], o[db][3]);
    }
}

// ============================================================================
// Combine split-K partials: O = (o0 + o1) / (l0 + l1), emit fp16-split pairs.
// Grid (ceil(NPIX/256), NCP); all streams unit-stride coalesced.
// ============================================================================
__global__ __launch_bounds__(256)
void attn_reduce()
{
    const int cp = blockIdx.y;
    const int n  = blockIdx.x * 256 + threadIdx.x;
    if (n >= NPIX) return;
    const int h  = cp >> 4;
    const int idx = cp * NPIX + n;
    float2 a0 = g_Po[0][idx];
    float2 a1 = g_Po[1][idx];
    float l = g_Pl[0][h * NPIX + n] + g_Pl[1][h * NPIX + n];
    float inv = 1.f / l;
    uint hi, lo;
    split_pair((a0.x + a1.x) * inv, (a0.y + a1.y) * inv, hi, lo);
    g_Oh2[idx] = hi;
    g_Ol2[idx] = lo;
}

// ============================================================================
extern "C" void kernel_launch(void* const* d_in, const int* in_sizes, int n_in,
                              void* d_out, int out_size)
{
    const float* query = (const float*)d_in[0];
    const float* q_w   = (const float*)d_in[1];
    const float* q_b   = (const float*)d_in[2];
    const float* k_w   = (const float*)d_in[3];
    const float* k_b   = (const float*)d_in[4];
    const float* v_w   = (const float*)d_in[5];
    const float* v_b   = (const float*)d_in[6];
    const float* p_w   = (const float*)d_in[7];
    const float* p_b   = (const float*)d_in[8];
    const float* lqw   = (const float*)d_in[9];
    float* out = (float*)d_out;

    split_wx<<<(NWP_TOT + NXP_TOT + 255) / 256, 256>>>(q_w, k_w, v_w, p_w, query);

    dim3 gq((NPIX + 63) / 64, 4, 3);                       // 65 x 4 x 3 = 780
    gemm_qkv<<<gq, 128>>>(q_b, k_b, v_b, lqw);

    dim3 ga((NPIX + 255) / 256, HEADS, NSPLIT);            // 17 x 8 x 2 = 272
    attn_kernel<<<ga, 512>>>();                            // -> g_Po/g_Pl

    dim3 gr((NPIX + 255) / 256, NCP, 1);                   // 17 x 128
    attn_reduce<<<gr, 256>>>();                            // -> g_Oh2/g_Ol2

    dim3 gp((NPIX + 63) / 64, 4, 1);                       // 65 x 4 = 260
    gemm_proj<<<gp, 128>>>(p_b, out);
}

// round 17
// speedup vs baseline: 1.4983x; 1.4983x over previous
#include <cuda_runtime.h>
#include <cuda_fp16.h>
#include <math.h>

#define NPIX 4140      // 46*90
#define CIN  256
#define HEADS 8
#define DHEAD 32
#define NTK  65        // key tiles of 64 (65*64 = 4160)
#define NSPLIT 2
#define TSPL 33        // tiles per split
#define LOG2E 1.4426950408889634f
#define NCP  (CIN / 2)              // 128 c-pairs

typedef unsigned int uint;

// ---------------- scratch (no allocations allowed) ----------------
__device__ float g_Q[CIN * NPIX];
__device__ float g_K[CIN * NPIX];
__device__ float g_V[CIN * NPIX];
__device__ float g_Po[NSPLIT][HEADS * NPIX * DHEAD];  // unnormalized o partials [h][q][d]
__device__ float g_Pl[NSPLIT][HEADS * NPIX];          // partial l
__device__ uint  g_Oh2[NCP * NPIX];     // attn out, fp16 hi pairs [cp][n]
__device__ uint  g_Ol2[NCP * NPIX];     // attn out, fp16 lo pairs
__device__ uint  g_Xh2[NCP * NPIX];     // query,  fp16 hi pairs [cp][n]
__device__ uint  g_Xl2[NCP * NPIX];     // query,  fp16 lo pairs
__device__ uint  g_Wh2[4 * CIN * NCP];  // q,k,v,p weights hi pairs [k][cp]
__device__ uint  g_Wl2[4 * CIN * NCP];  // weights lo pairs
__device__ float g_Lq[NTK * 64];        // log-quad bias * log2(e), padded

// ---------------- helpers ----------------
__device__ __forceinline__ float ex2(float x) {
    float y;
    asm("ex2.approx.f32 %0, %1;" : "=f"(y) : "f"(x));
    return y;
}

__device__ __forceinline__ uint packh2(float a, float b) {
    uint r;
    asm("cvt.rn.f16x2.f32 %0, %2, %1;" : "=r"(r) : "f"(a), "f"(b));
    return r;
}

__device__ __forceinline__ float2 unpackh2(uint u) {
    __half2 h = *reinterpret_cast<__half2*>(&u);
    return make_float2(__low2float(h), __high2float(h));
}

__device__ __forceinline__ void split_pair(float a, float b, uint& hi, uint& lo) {
    hi = packh2(a, b);
    float2 hv = unpackh2(hi);
    lo = packh2(a - hv.x, b - hv.y);
}

__device__ __forceinline__ void mma_f16(float c[4],
                                        uint a0, uint a1, uint a2, uint a3,
                                        uint b0, uint b1) {
    asm volatile(
        "mma.sync.aligned.m16n8k16.row.col.f32.f16.f16.f32 "
        "{%0,%1,%2,%3}, {%4,%5,%6,%7}, {%8,%9}, {%0,%1,%2,%3};"
        : "+f"(c[0]), "+f"(c[1]), "+f"(c[2]), "+f"(c[3])
        : "r"(a0), "r"(a1), "r"(a2), "r"(a3), "r"(b0), "r"(b1));
}

__device__ __forceinline__ void ldsm_x4(uint& r0, uint& r1, uint& r2, uint& r3,
                                        uint addr) {
    asm volatile("ldmatrix.sync.aligned.m8n8.x4.shared.b16 {%0,%1,%2,%3}, [%4];"
                 : "=r"(r0), "=r"(r1), "=r"(r2), "=r"(r3) : "r"(addr));
}
__device__ __forceinline__ void ldsm_x4_t(uint& r0, uint& r1, uint& r2, uint& r3,
                                          uint addr) {
    asm volatile("ldmatrix.sync.aligned.m8n8.x4.trans.shared.b16 {%0,%1,%2,%3}, [%4];"
                 : "=r"(r0), "=r"(r1), "=r"(r2), "=r"(r3) : "r"(addr));
}

__device__ __forceinline__ void cp_async16(void* dst, const void* src, int src_sz) {
    uint d = (uint)__cvta_generic_to_shared(dst);
    asm volatile("cp.async.cg.shared.global [%0], [%1], 16, %2;"
                 :: "r"(d), "l"(src), "r"(src_sz));
}
__device__ __forceinline__ void cp_commit() { asm volatile("cp.async.commit_group;"); }
__device__ __forceinline__ void cp_wait0()  { asm volatile("cp.async.wait_group 0;"); }

// ============================================================================
// Pre-split weights AND query -> fp16 (hi,lo) c-pairs (single launch)
// ============================================================================
#define NWP_TOT (4 * CIN * NCP)        // 131072 pair entries
#define NXP_TOT (NCP * NPIX)           // 529920 pair entries

__global__ __launch_bounds__(256)
void split_wx(const float* __restrict__ qw, const float* __restrict__ kw,
              const float* __restrict__ vw, const float* __restrict__ pw,
              const float* __restrict__ query)
{
    int i = blockIdx.x * 256 + threadIdx.x;
    if (i < NWP_TOT) {
        int m   = i >> 15;
        int rem = i & 32767;
        int k   = rem >> 7;
        int cp  = rem & 127;
        const float* W = (m == 0) ? qw : (m == 1) ? kw : (m == 2) ? vw : pw;
        uint hi, lo;
        split_pair(W[k * CIN + 2 * cp], W[k * CIN + 2 * cp + 1], hi, lo);
        g_Wh2[i] = hi;
        g_Wl2[i] = lo;
    } else {
        int j = i - NWP_TOT;
        if (j < NXP_TOT) {
            int cp = j / NPIX;
            int n  = j - cp * NPIX;
            uint hi, lo;
            split_pair(query[(2 * cp) * NPIX + n], query[(2 * cp + 1) * NPIX + n], hi, lo);
            g_Xh2[j] = hi;
            g_Xl2[j] = lo;
        }
    }
}

// ============================================================================
// 3-term fp16-split GEMM (hh + hl + lh), m16n8k16, pre-split operands.
// Tile 64k x 64n, 128 thr / 4 warps. k-step 32 (16 c-pairs), double-buffered.
// ============================================================================
#define WST 20
#define XST 72

__device__ __forceinline__
void gemm_core(const uint* __restrict__ Xh2, const uint* __restrict__ Xl2,
               const uint* __restrict__ Wh2, const uint* __restrict__ Wl2,
               const float* __restrict__ bias, float* __restrict__ Y)
{
    __shared__ uint sWh[2][64 * WST], sWl[2][64 * WST];
    __shared__ uint sXh[2][16 * XST], sXl[2][16 * XST];

    const int tid  = threadIdx.x;
    const int w    = tid >> 5;
    const int lane = tid & 31;
    const int g    = lane >> 2;
    const int tig  = lane & 3;
    const int k0   = blockIdx.y * 64;
    const int n0   = blockIdx.x * 64;

    {
        #pragma unroll
        for (int r = 0; r < 2; r++) {
            int idx = tid + 128 * r;
            int wk = idx >> 2, wcp = (idx & 3) * 4;
            cp_async16(&sWh[0][wk * WST + wcp], &Wh2[(k0 + wk) * NCP + wcp], 16);
            cp_async16(&sWl[0][wk * WST + wcp], &Wl2[(k0 + wk) * NCP + wcp], 16);
        }
        #pragma unroll
        for (int r = 0; r < 2; r++) {
            int idx = tid + 128 * r;
            int xcp = idx >> 4, xn = (idx & 15) * 4;
            int n = n0 + xn;
            int ok = (n < NPIX);
            cp_async16(&sXh[0][xcp * XST + xn], &Xh2[xcp * NPIX + (ok ? n : 0)], ok ? 16 : 0);
            cp_async16(&sXl[0][xcp * XST + xn], &Xl2[xcp * NPIX + (ok ? n : 0)], ok ? 16 : 0);
        }
        cp_commit();
    }

    float acc[8][4];
    #pragma unroll
    for (int nb = 0; nb < 8; nb++)
        #pragma unroll
        for (int i = 0; i < 4; i++) acc[nb][i] = 0.f;

    cp_wait0();
    __syncthreads();

    #pragma unroll
    for (int it = 0; it < 8; it++) {
        const int cur = it & 1;
        const int nxt = cur ^ 1;
        const bool more = (it + 1 < 8);

        if (more) {
            const int cc2 = (it + 1) * 16;
            #pragma unroll
            for (int r = 0; r < 2; r++) {
                int idx = tid + 128 * r;
                int wk = idx >> 2, wcp = (idx & 3) * 4;
                cp_async16(&sWh[nxt][wk * WST + wcp],
                           &Wh2[(k0 + wk) * NCP + cc2 + wcp], 16);
                cp_async16(&sWl[nxt][wk * WST + wcp],
                           &Wl2[(k0 + wk) * NCP + cc2 + wcp], 16);
            }
            #pragma unroll
            for (int r = 0; r < 2; r++) {
                int idx = tid + 128 * r;
                int xcp = idx >> 4, xn = (idx & 15) * 4;
                int n = n0 + xn;
                int ok = (n < NPIX);
                cp_async16(&sXh[nxt][xcp * XST + xn],
                           &Xh2[(cc2 + xcp) * NPIX + (ok ? n : 0)], ok ? 16 : 0);
                cp_async16(&sXl[nxt][xcp * XST + xn],
                           &Xl2[(cc2 + xcp) * NPIX + (ok ? n : 0)], ok ? 16 : 0);
            }
            cp_commit();
        }

        #pragma unroll
        for (int kb = 0; kb < 2; kb++) {
            const int ar = (w * 16 + g) * WST + kb * 8 + tig;
            uint ah0 = sWh[cur][ar];
            uint ah1 = sWh[cur][ar + 8 * WST];
            uint ah2 = sWh[cur][ar + 4];
            uint ah3 = sWh[cur][ar + 8 * WST + 4];
            uint al0 = sWl[cur][ar];
            uint al1 = sWl[cur][ar + 8 * WST];
            uint al2 = sWl[cur][ar + 4];
            uint al3 = sWl[cur][ar + 8 * WST + 4];
            const int br0 = (kb * 8 + tig) * XST + g;
            const int br1 = br0 + 4 * XST;
            #pragma unroll
            for (int nb = 0; nb < 8; nb++) {
                uint bh0 = sXh[cur][br0 + nb * 8];
                uint bh1 = sXh[cur][br1 + nb * 8];
                uint bl0 = sXl[cur][br0 + nb * 8];
                uint bl1 = sXl[cur][br1 + nb * 8];
                mma_f16(acc[nb], ah0, ah1, ah2, ah3, bh0, bh1);
                mma_f16(acc[nb], ah0, ah1, ah2, ah3, bl0, bl1);
                mma_f16(acc[nb], al0, al1, al2, al3, bh0, bh1);
            }
        }

        if (more) cp_wait0();
        __syncthreads();
    }

    const int r0 = k0 + w * 16 + g;
    const int r1 = r0 + 8;
    const float bv0 = __ldg(&bias[r0]);
    const float bv1 = __ldg(&bias[r1]);
    #pragma unroll
    for (int nb = 0; nb < 8; nb++) {
        int n = n0 + nb * 8 + 2 * tig;
        if (n < NPIX) {
            float2 y0 = make_float2(acc[nb][0] + bv0, acc[nb][1] + bv0);
            float2 y1 = make_float2(acc[nb][2] + bv1, acc[nb][3] + bv1);
            *(float2*)&Y[r0 * NPIX + n] = y0;
            *(float2*)&Y[r1 * NPIX + n] = y1;
        }
    }
}

__global__ __launch_bounds__(128)
void gemm_qkv(const float* __restrict__ qb, const float* __restrict__ kb,
              const float* __restrict__ vb, const float* __restrict__ lq)
{
    int z = blockIdx.z;
    if (z == 0 && blockIdx.x == 0 && blockIdx.y == 0) {
        for (int i = threadIdx.x; i < NTK * 64; i += 128)
            g_Lq[i] = (i < NPIX) ? lq[i] * LOG2E : -1e30f;
    }
    const float* B = (z == 0) ? qb : (z == 1) ? kb : vb;
    float* Y       = (z == 0) ? g_Q : (z == 1) ? g_K : g_V;
    gemm_core(g_Xh2, g_Xl2, g_Wh2 + z * CIN * NCP, g_Wl2 + z * CIN * NCP, B, Y);
}

__global__ __launch_bounds__(128)
void gemm_proj(const float* __restrict__ B, float* __restrict__ Y)
{
    gemm_core(g_Oh2, g_Ol2, g_Wh2 + 3 * CIN * NCP, g_Wl2 + 3 * CIN * NCP, B, Y);
}

// ============================================================================
// Flash attention, fp16 m16n8k16, fixed-shift base-2 softmax, split-K (z=0,1),
// K/V fragments via ldmatrix. Partials written [h][q][d] (producer-coalesced:
// each quad stores 32B contiguous); attn_reduce transposes via smem.
//   Grid 17 x 8 x 2 = 272 blocks of 512 thr -> 2 CTAs/SM (32 warps/SM).
// ============================================================================
#define KSW 36     // words per K d-row (64 keys f16 = 32 words + 4 pad)
#define VSW 36     // words per V d-row (32 key-pair words + 4 pad)

__global__ __launch_bounds__(512, 2)
void attn_kernel()
{
    __shared__ uint sK[2][32 * KSW];
    __shared__ uint sV[2][32 * VSW];

    const int tid  = threadIdx.x;
    const int lane = tid & 31;
    const int w    = tid >> 5;
    const int g    = lane >> 2;
    const int tig  = lane & 3;
    const int h    = blockIdx.y;
    const int qb   = blockIdx.x;
    const int z    = blockIdx.z;

    const int t0    = z * TSPL;
    const int t_end = (t0 + TSPL < NTK) ? (t0 + TSPL) : NTK;

    const int q_row0 = qb * 256 + w * 16 + g;
    const int q_row1 = q_row0 + 8;

    const int fd  = tid >> 4;
    const int fkc = tid & 15;

    const uint skb0 = (uint)__cvta_generic_to_shared(&sK[0][0]);
    const uint skb1 = (uint)__cvta_generic_to_shared(&sK[1][0]);
    const uint svb0 = (uint)__cvta_generic_to_shared(&sV[0][0]);
    const uint svb1 = (uint)__cvta_generic_to_shared(&sV[1][0]);

    const uint koff = (uint)lane * KSW;
    const uint vrow = ((lane >> 4) * 8 + (lane & 7)) * VSW + ((lane >> 3) & 1) * 4;

    // ---- Q fragments, fp16 (scale includes log2 e) ----
    const float scale = 0.17677669529663687f * LOG2E;
    const int r0 = (q_row0 < NPIX) ? q_row0 : (NPIX - 1);
    const int r1 = (q_row1 < NPIX) ? q_row1 : (NPIX - 1);
    uint qa[2][4];
    #pragma unroll
    for (int kc = 0; kc < 2; kc++) {
        int d0 = kc * 16 + 2 * tig;
        const float* Qh = g_Q + (size_t)h * DHEAD * NPIX;
        qa[kc][0] = packh2(Qh[(d0)     * NPIX + r0] * scale, Qh[(d0 + 1) * NPIX + r0] * scale);
        qa[kc][1] = packh2(Qh[(d0)     * NPIX + r1] * scale, Qh[(d0 + 1) * NPIX + r1] * scale);
        qa[kc][2] = packh2(Qh[(d0 + 8) * NPIX + r0] * scale, Qh[(d0 + 9) * NPIX + r0] * scale);
        qa[kc][3] = packh2(Qh[(d0 + 8) * NPIX + r1] * scale, Qh[(d0 + 9) * NPIX + r1] * scale);
    }

    float o[4][4];
    #pragma unroll
    for (int db = 0; db < 4; db++)
        #pragma unroll
        for (int j = 0; j < 4; j++) o[db][j] = 0.f;

    float l0 = 0.f, l1 = 0.f;
    float4 rk, rv;

    const float* Kbase = g_K + (size_t)h * DHEAD * NPIX;
    const float* Vbase = g_V + (size_t)h * DHEAD * NPIX;

    // ---------- prologue ----------
    {
        int key0 = t0 * 64 + fkc * 4;
        rk = *(const float4*)&Kbase[fd * NPIX + key0];
        rv = *(const float4*)&Vbase[fd * NPIX + key0];
        uint2 kk = make_uint2(packh2(rk.x, rk.y), packh2(rk.z, rk.w));
        uint2 vv = make_uint2(packh2(rv.x, rv.y), packh2(rv.z, rv.w));
        *(uint2*)&sK[0][fd * KSW + fkc * 2] = kk;
        *(uint2*)&sV[0][fd * VSW + fkc * 2] = vv;
    }
    __syncthreads();

    for (int t = t0; t < t_end; t++) {
        const int cur = (t - t0) & 1;
        const bool more = (t + 1 < t_end);
        const uint skc = cur ? skb1 : skb0;
        const uint svc = cur ? svb1 : svb0;

        if (more) {
            int key0 = (t + 1) * 64 + fkc * 4;
            bool ok = (key0 < NPIX);
            int keyc = ok ? key0 : 0;
            float4 ka = *(const float4*)&Kbase[fd * NPIX + keyc];
            float4 va = *(const float4*)&Vbase[fd * NPIX + keyc];
            rk = ok ? ka : make_float4(0.f, 0.f, 0.f, 0.f);
            rv = ok ? va : make_float4(0.f, 0.f, 0.f, 0.f);
        }

        // ---- S = Q K^T ----
        float c[8][4];
        #pragma unroll
        for (int nb = 0; nb < 8; nb++) {
            c[nb][0] = c[nb][1] = c[nb][2] = c[nb][3] = 0.f;
            uint b00, b01, b10, b11;
            ldsm_x4_t(b00, b01, b10, b11, skc + (koff + nb * 4) * 4);
            mma_f16(c[nb], qa[0][0], qa[0][1], qa[0][2], qa[0][3], b00, b01);
            mma_f16(c[nb], qa[1][0], qa[1][1], qa[1][2], qa[1][3], b10, b11);
        }

        // ---- fused bias + exp2 + pack + PV ----
        #pragma unroll
        for (int kc = 0; kc < 4; kc++) {
            const int nb0 = 2 * kc, nb1 = 2 * kc + 1;
            float2 lb0 = *(const float2*)&g_Lq[t * 64 + nb0 * 8 + 2 * tig];
            float2 lb1 = *(const float2*)&g_Lq[t * 64 + nb1 * 8 + 2 * tig];
            float p00 = ex2(c[nb0][0] + lb0.x);
            float p01 = ex2(c[nb0][1] + lb0.y);
            float p02 = ex2(c[nb0][2] + lb0.x);
            float p03 = ex2(c[nb0][3] + lb0.y);
            float p10 = ex2(c[nb1][0] + lb1.x);
            float p11 = ex2(c[nb1][1] + lb1.y);
            float p12 = ex2(c[nb1][2] + lb1.x);
            float p13 = ex2(c[nb1][3] + lb1.y);
            l0 += (p00 + p01) + (p10 + p11);
            l1 += (p02 + p03) + (p12 + p13);
            uint pa0 = packh2(p00, p01);
            uint pa1 = packh2(p02, p03);
            uint pa2 = packh2(p10, p11);
            uint pa3 = packh2(p12, p13);
            #pragma unroll
            for (int dbp = 0; dbp < 2; dbp++) {
                uint v00, v01, v10, v11;
                uint addr = svc + (vrow + dbp * 16 * VSW + kc * 8) * 4;
                ldsm_x4(v00, v01, v10, v11, addr);
                mma_f16(o[2 * dbp],     pa0, pa1, pa2, pa3, v00, v01);
                mma_f16(o[2 * dbp + 1], pa0, pa1, pa2, pa3, v10, v11);
            }
        }

        if (more) {
            const int nxt = cur ^ 1;
            uint2 kk = make_uint2(packh2(rk.x, rk.y), packh2(rk.z, rk.w));
            uint2 vv = make_uint2(packh2(rv.x, rv.y), packh2(rv.z, rv.w));
            *(uint2*)&sK[nxt][fd * KSW + fkc * 2] = kk;
            *(uint2*)&sV[nxt][fd * VSW + fkc * 2] = vv;
        }
        __syncthreads();
    }

    // ---- partial epilogue: quad-reduce l, write unnormalized partials ----
    l0 += __shfl_xor_sync(0xffffffffu, l0, 1);
    l0 += __shfl_xor_sync(0xffffffffu, l0, 2);
    l1 += __shfl_xor_sync(0xffffffffu, l1, 1);
    l1 += __shfl_xor_sync(0xffffffffu, l1, 2);
    if (tig == 0) {
        if (q_row0 < NPIX) g_Pl[z][h * NPIX + q_row0] = l0;
        if (q_row1 < NPIX) g_Pl[z][h * NPIX + q_row1] = l1;
    }
    #pragma unroll
    for (int db = 0; db < 4; db++) {
        int d = db * 8 + 2 * tig;
        if (q_row0 < NPIX)
            *(float2*)&g_Po[z][((size_t)h * NPIX + q_row0) * DHEAD + d] =
                make_float2(o[db][0], o[db][1]);
        if (q_row1 < NPIX)
            *(float2*)&g_Po[z][((size_t)h * NPIX + q_row1) * DHEAD + d] =
                make_float2(o[db][2], o[db][3]);
    }
}

// ============================================================================
// Combine split-K partials with a smem transpose:
//   reads  g_Po [h][q][d]  (coalesced: 128B per q-row, warp covers 2 rows)
//   writes g_Oh2/g_Ol2 [cp][n] (coalesced: 64 consecutive n per dp row)
// Grid (ceil(NPIX/64), HEADS), 256 threads.
// ============================================================================
#define RST 69      // smem row stride (conflict-free both phases)

__global__ __launch_bounds__(256)
void attn_reduce()
{
    __shared__ uint  sHi[16 * RST], sLo[16 * RST];
    __shared__ float sInv[64];

    const int h   = blockIdx.y;
    const int q0  = blockIdx.x * 64;
    const int tid = threadIdx.x;

    if (tid < 64) {
        int q = q0 + tid;
        float l = 1.f;
        if (q < NPIX) l = g_Pl[0][h * NPIX + q] + g_Pl[1][h * NPIX + q];
        sInv[tid] = 1.f / l;
    }
    __syncthreads();

    #pragma unroll
    for (int r = 0; r < 4; r++) {
        int i  = tid + 256 * r;          // 0..1023
        int q  = i >> 4;                  // 0..63
        int dp = i & 15;                  // 0..15
        int qg = q0 + q;
        float2 a0 = make_float2(0.f, 0.f), a1 = a0;
        if (qg < NPIX) {
            size_t ob = ((size_t)h * NPIX + qg) * DHEAD + 2 * dp;
            a0 = *(const float2*)&g_Po[0][ob];
            a1 = *(const float2*)&g_Po[1][ob];
        }
        float inv = sInv[q];
        uint hi, lo;
        split_pair((a0.x + a1.x) * inv, (a0.y + a1.y) * inv, hi, lo);
        sHi[dp * RST + q] = hi;
        sLo[dp * RST + q] = lo;
    }
    __syncthreads();

    #pragma unroll
    for (int r = 0; r < 4; r++) {
        int i  = tid + 256 * r;
        int dp = i >> 6;                  // 0..15
        int q  = i & 63;
        int qg = q0 + q;
        if (qg < NPIX) {
            int cp = h * 16 + dp;
            g_Oh2[cp * NPIX + qg] = sHi[dp * RST + q];
            g_Ol2[cp * NPIX + qg] = sLo[dp * RST + q];
        }
    }
}

// ============================================================================
extern "C" void kernel_launch(void* const* d_in, const int* in_sizes, int n_in,
                              void* d_out, int out_size)
{
    const float* query = (const float*)d_in[0];
    const float* q_w   = (const float*)d_in[1];
    const float* q_b   = (const float*)d_in[2];
    const float* k_w   = (const float*)d_in[3];
    const float* k_b   = (const float*)d_in[4];
    const float* v_w   = (const float*)d_in[5];
    const float* v_b   = (const float*)d_in[6];
    const float* p_w   = (const float*)d_in[7];
    const float* p_b   = (const float*)d_in[8];
    const float* lqw   = (const float*)d_in[9];
    float* out = (float*)d_out;

    split_wx<<<(NWP_TOT + NXP_TOT + 255) / 256, 256>>>(q_w, k_w, v_w, p_w, query);

    dim3 gq((NPIX + 63) / 64, 4, 3);                       // 65 x 4 x 3 = 780
    gemm_qkv<<<gq, 128>>>(q_b, k_b, v_b, lqw);

    dim3 ga((NPIX + 255) / 256, HEADS, NSPLIT);            // 17 x 8 x 2 = 272
    attn_kernel<<<ga, 512>>>();                            // -> g_Po/g_Pl

    dim3 gr((NPIX + 63) / 64, HEADS, 1);                   // 65 x 8 = 520
    attn_reduce<<<gr, 256>>>();                            // -> g_Oh2/g_Ol2

    dim3 gp((NPIX + 63) / 64, 4, 1);                       // 65 x 4 = 260
    gemm_proj<<<gp, 128>>>(p_b, out);
}